// round 4
// baseline (speedup 1.0000x reference)
#include <cuda_runtime.h>
#include <cstdint>

// ---------------------------------------------------------------------------
// GCNConv: out = X@H0 + A@(X@H1) + A^2@(X@H2)
//   Restructured:  out = Y0 + A@(Y1 + A@Y2),  [Y0|Y1|Y2] = X @ [H0|H1|H2]
// Round 4: split GEMM by dependency — Y1,Y2 first (SpMM-1 needs them), Y0
//   concurrent with SpMM-1 (only SpMM-2 needs it). CSR build overlaps Y1,Y2.
// ---------------------------------------------------------------------------

#define N_NODES_MAX 100000
#define N_EDGES_MAX 3200000
#define FDIM 128

__device__ float g_buf1[(size_t)N_NODES_MAX * FDIM];
__device__ float g_buf2[(size_t)N_NODES_MAX * FDIM];
__device__ int   g_rowptr[N_NODES_MAX + 1];
__device__ int   g_cursor[N_NODES_MAX + 1];
__device__ int   g_bsum[1024];
__device__ int2  g_ecv[N_EDGES_MAX];

// ---------------------------------------------------------------------------
// GEMM: dst_k = X @ H[k] for k = kOff + blockIdx.y.
// 128x128 tile, BK=16, 256 threads, 8x8 microtile, fp32.
// ---------------------------------------------------------------------------
__global__ __launch_bounds__(256, 2)
void gemm_kernel(const float* __restrict__ X, const float* __restrict__ H,
                 float* __restrict__ out0, float* __restrict__ out1,
                 float* __restrict__ out2, int nN, int kOff)
{
    const int kSel = kOff + blockIdx.y;
    float* dst = (kSel == 0) ? out0 : ((kSel == 1) ? out1 : out2);
    const float* Hk = H + (size_t)kSel * FDIM * FDIM;
    const int rowBase = blockIdx.x * 128;

    __shared__ float Xs[16][128 + 4];
    __shared__ float Hs[16][128];

    const int tid  = threadIdx.x;
    const int tRow = (tid >> 4) << 3;
    const int tCol = (tid & 15) << 3;

    float acc[8][8];
#pragma unroll
    for (int i = 0; i < 8; i++)
#pragma unroll
        for (int j = 0; j < 8; j++) acc[i][j] = 0.f;

#pragma unroll
    for (int k0 = 0; k0 < FDIM; k0 += 16) {
#pragma unroll
        for (int i = 0; i < 2; i++) {
            int id = tid + i * 256;
            int m  = id >> 2;
            int kk = (id & 3) << 2;
            float4 v = make_float4(0.f, 0.f, 0.f, 0.f);
            int gr = rowBase + m;
            if (gr < nN)
                v = *(const float4*)(X + (size_t)gr * FDIM + k0 + kk);
            Xs[kk + 0][m] = v.x;
            Xs[kk + 1][m] = v.y;
            Xs[kk + 2][m] = v.z;
            Xs[kk + 3][m] = v.w;
        }
#pragma unroll
        for (int i = 0; i < 2; i++) {
            int id = tid + i * 256;
            int kk = id >> 5;
            int c  = (id & 31) << 2;
            *(float4*)&Hs[kk][c] = *(const float4*)(Hk + (size_t)(k0 + kk) * FDIM + c);
        }
        __syncthreads();

#pragma unroll
        for (int kk = 0; kk < 16; kk++) {
            float a[8], b[8];
            *(float4*)&a[0] = *(const float4*)&Xs[kk][tRow];
            *(float4*)&a[4] = *(const float4*)&Xs[kk][tRow + 4];
            *(float4*)&b[0] = *(const float4*)&Hs[kk][tCol];
            *(float4*)&b[4] = *(const float4*)&Hs[kk][tCol + 4];
#pragma unroll
            for (int i = 0; i < 8; i++)
#pragma unroll
                for (int j = 0; j < 8; j++)
                    acc[i][j] += a[i] * b[j];
        }
        __syncthreads();
    }

#pragma unroll
    for (int i = 0; i < 8; i++) {
        int gr = rowBase + tRow + i;
        if (gr < nN) {
            float* drow = dst + (size_t)gr * FDIM + tCol;
            *(float4*)(drow + 0) = make_float4(acc[i][0], acc[i][1], acc[i][2], acc[i][3]);
            *(float4*)(drow + 4) = make_float4(acc[i][4], acc[i][5], acc[i][6], acc[i][7]);
        }
    }
}

// ---------------------------------------------------------------------------
// CSR build
// ---------------------------------------------------------------------------
__global__ void hist_kernel(const int* __restrict__ rows, int* __restrict__ cnt, int nE)
{
    int e = blockIdx.x * 256 + threadIdx.x;
    if (e < nE) atomicAdd(&cnt[rows[e]], 1);
}

__global__ __launch_bounds__(256)
void scan1_kernel(const int* __restrict__ cnt, int* __restrict__ pre,
                  int* __restrict__ bsum, int nN)
{
    const int t    = threadIdx.x;
    const int base = blockIdx.x * 1024 + t * 4;
    const int lane = t & 31, warp = t >> 5;

    int v[4];
#pragma unroll
    for (int j = 0; j < 4; j++) v[j] = (base + j < nN) ? cnt[base + j] : 0;
    const int s = v[0] + v[1] + v[2] + v[3];

    int incl = s;
#pragma unroll
    for (int off = 1; off < 32; off <<= 1) {
        int n = __shfl_up_sync(0xFFFFFFFFu, incl, off);
        if (lane >= off) incl += n;
    }

    __shared__ int wsum[8];
    if (lane == 31) wsum[warp] = incl;
    __syncthreads();
    if (t < 8) {
        int w = wsum[t];
        int wincl = w;
#pragma unroll
        for (int off = 1; off < 8; off <<= 1) {
            int n = __shfl_up_sync(0xFFu, wincl, off);
            if (t >= off) wincl += n;
        }
        wsum[t] = wincl - w;
    }
    __syncthreads();

    int run = incl - s + wsum[warp];
#pragma unroll
    for (int j = 0; j < 4; j++) {
        if (base + j < nN) pre[base + j] = run;
        run += v[j];
    }
    if (t == 255) bsum[blockIdx.x] = run;
}

__global__ __launch_bounds__(1024)
void scan2_kernel(int* __restrict__ bsum, int* __restrict__ total_out, int B)
{
    __shared__ int sh[1024];
    const int t = threadIdx.x;
    int v = (t < B) ? bsum[t] : 0;
    sh[t] = v;
    __syncthreads();
    for (int off = 1; off < 1024; off <<= 1) {
        int a = (t >= off) ? sh[t - off] : 0;
        __syncthreads();
        sh[t] += a;
        __syncthreads();
    }
    if (t < B) bsum[t] = sh[t] - v;
    if (t == 1023) *total_out = sh[1023];
}

__global__ void scan3_kernel(int* __restrict__ rowptr, const int* __restrict__ bsum,
                             int* __restrict__ cursor, int nN)
{
    int i = blockIdx.x * 256 + threadIdx.x;
    if (i < nN) {
        int val = rowptr[i] + __ldg(bsum + (i >> 10));
        rowptr[i] = val;
        cursor[i] = val;
    }
}

__global__ void scatter_kernel(const int* __restrict__ rows, const int* __restrict__ cols,
                               const float* __restrict__ vals, int* __restrict__ cursor,
                               int2* __restrict__ ecv, int nE)
{
    int e = blockIdx.x * 256 + threadIdx.x;
    if (e < nE) {
        int r   = rows[e];
        int pos = atomicAdd(&cursor[r], 1);
        ecv[pos] = make_int2(cols[e], __float_as_int(vals[e]));
    }
}

// ---------------------------------------------------------------------------
// SpMM (CSR): warp per dest row, register accumulation, NO atomics.
// ---------------------------------------------------------------------------
__global__ __launch_bounds__(256)
void spmm_csr_kernel(const int* __restrict__ rowptr, const int2* __restrict__ ecv,
                     const float* __restrict__ src, float* __restrict__ dst, int nN)
{
    const int w = (blockIdx.x * 256 + threadIdx.x) >> 5;
    if (w >= nN) return;
    const int lane  = threadIdx.x & 31;
    const int start = __ldg(rowptr + w);
    const int end   = __ldg(rowptr + w + 1);

    float4 acc = make_float4(0.f, 0.f, 0.f, 0.f);

#pragma unroll 4
    for (int i = start; i < end; i++) {
        int2  cv = __ldg(ecv + i);
        float v  = __int_as_float(cv.y);
        float4 s = __ldg((const float4*)(src + (size_t)cv.x * FDIM) + lane);
        acc.x += v * s.x;
        acc.y += v * s.y;
        acc.z += v * s.z;
        acc.w += v * s.w;
    }

    float4* d  = (float4*)(dst + (size_t)w * FDIM) + lane;
    float4 cur = *d;
    cur.x += acc.x; cur.y += acc.y; cur.z += acc.z; cur.w += acc.w;
    *d = cur;
}

// ---------------------------------------------------------------------------
extern "C" void kernel_launch(void* const* d_in, const int* in_sizes, int n_in,
                              void* d_out, int out_size)
{
    const int*   rows = (const int*)d_in[0];
    const int*   cols = (const int*)d_in[1];
    const float* vals = (const float*)d_in[2];
    const float* x    = (const float*)d_in[3];
    const float* H    = (const float*)d_in[4];
    float*       out  = (float*)d_out;

    const int nE = in_sizes[0];
    const int nN = in_sizes[3] / FDIM;

    float *buf1, *buf2;
    int *rowptr, *cursor, *bsum;
    int2 *ecv;
    cudaGetSymbolAddress((void**)&buf1, g_buf1);
    cudaGetSymbolAddress((void**)&buf2, g_buf2);
    cudaGetSymbolAddress((void**)&rowptr, g_rowptr);
    cudaGetSymbolAddress((void**)&cursor, g_cursor);
    cudaGetSymbolAddress((void**)&bsum, g_bsum);
    cudaGetSymbolAddress((void**)&ecv, g_ecv);

    static cudaStream_t sGemm = nullptr;
    static cudaEvent_t  evFork = nullptr, evG12 = nullptr, evG0 = nullptr;
    if (sGemm == nullptr) {
        cudaStreamCreateWithFlags(&sGemm, cudaStreamNonBlocking);
        cudaEventCreateWithFlags(&evFork, cudaEventDisableTiming);
        cudaEventCreateWithFlags(&evG12, cudaEventDisableTiming);
        cudaEventCreateWithFlags(&evG0, cudaEventDisableTiming);
    }

    const int eBlocks = (nE + 255) / 256;
    const int nBlocks = (nN + 255) / 256;
    const int B       = (nN + 1023) / 1024;
    const int mTiles  = (nN + 127) / 128;

    // ---- fork: GEMMs on side stream, ordered by downstream need ----
    cudaEventRecord(evFork, 0);
    cudaStreamWaitEvent(sGemm, evFork, 0);
    // Y1 -> buf1, Y2 -> buf2 (kOff=1, grid.y=2): needed by SpMM-1
    gemm_kernel<<<dim3(mTiles, 2, 1), 256, 0, sGemm>>>(x, H, out, buf1, buf2, nN, 1);
    cudaEventRecord(evG12, sGemm);
    // Y0 -> out (kOff=0): needed only by SpMM-2; overlaps SpMM-1
    gemm_kernel<<<dim3(mTiles, 1, 1), 256, 0, sGemm>>>(x, H, out, buf1, buf2, nN, 0);
    cudaEventRecord(evG0, sGemm);

    // ---- CSR build on main stream (overlaps Y1,Y2 GEMM) ----
    cudaMemsetAsync(cursor, 0, (size_t)nN * sizeof(int), 0);
    hist_kernel<<<eBlocks, 256>>>(rows, cursor, nE);
    scan1_kernel<<<B, 256>>>(cursor, rowptr, bsum, nN);
    scan2_kernel<<<1, 1024>>>(bsum, rowptr + nN, B);
    scan3_kernel<<<nBlocks, 256>>>(rowptr, bsum, cursor, nN);
    scatter_kernel<<<eBlocks, 256>>>(rows, cols, vals, cursor, ecv, nE);

    // ---- SpMM-1 after Y1,Y2; SpMM-2 additionally after Y0 ----
    const int spmmBlocks = (int)(((long long)nN * 32 + 255) / 256);
    cudaStreamWaitEvent(0, evG12, 0);
    spmm_csr_kernel<<<spmmBlocks, 256>>>(rowptr, ecv, buf2, buf1, nN);  // buf1 = Y1 + A@Y2
    cudaStreamWaitEvent(0, evG0, 0);
    spmm_csr_kernel<<<spmmBlocks, 256>>>(rowptr, ecv, buf1, out, nN);   // out  = Y0 + A@buf1
}

// round 5
// speedup vs baseline: 1.2421x; 1.2421x over previous
#include <cuda_runtime.h>
#include <mma.h>
#include <cstdint>

using namespace nvcuda;

// ---------------------------------------------------------------------------
// GCNConv: out = X@H0 + A@(X@H1) + A^2@(X@H2)
//   Restructured:  out = Y0 + A@(Y1 + A@Y2),  [Y0|Y1|Y2] = X @ [H0|H1|H2]
// Round 5: R3 orchestration (fork CSR build under GEMM, join, 2x SpMM) but
//   the GEMM now runs on tensor cores via wmma TF32 (m16n16k8).
// ---------------------------------------------------------------------------

#define N_NODES_MAX 100000
#define N_EDGES_MAX 3200000
#define FDIM 128

__device__ float g_buf1[(size_t)N_NODES_MAX * FDIM];
__device__ float g_buf2[(size_t)N_NODES_MAX * FDIM];
__device__ int   g_rowptr[N_NODES_MAX + 1];
__device__ int   g_cursor[N_NODES_MAX + 1];
__device__ int   g_bsum[1024];
__device__ int2  g_ecv[N_EDGES_MAX];

// ---------------------------------------------------------------------------
// TF32 GEMM: dst_k = X @ H[k], k = blockIdx.y in {0,1,2}.
// 128x128 tile, BK=32, 256 threads (8 warps in 2x4), each warp 64x32 via
// 4x2 wmma m16n16k8 fragments. fp32 accumulate.
// ---------------------------------------------------------------------------
#define XS_LD 36   // 32 + 4 pad (multiple of 4 elems for ldm)
#define HS_LD 132  // 128 + 4 pad

__global__ __launch_bounds__(256, 2)
void gemm3_tf32_kernel(const float* __restrict__ X, const float* __restrict__ H,
                       float* __restrict__ out0, float* __restrict__ out1,
                       float* __restrict__ out2, int nN)
{
    const int kSel = blockIdx.y;
    float* dst = (kSel == 0) ? out0 : ((kSel == 1) ? out1 : out2);
    const float* Hk = H + (size_t)kSel * FDIM * FDIM;
    const int rowBase = blockIdx.x * 128;

    __shared__ float Xs[128 * XS_LD];      // [m][k]
    __shared__ float Hs[32 * HS_LD];       // [k][n]
    __shared__ float Stage[8][16 * 17];    // per-warp boundary staging

    const int tid   = threadIdx.x;
    const int warp  = tid >> 5;
    const int lane  = tid & 31;
    const int warpM = (warp & 1) * 64;     // 0 or 64
    const int warpN = (warp >> 1) * 32;    // 0,32,64,96

    wmma::fragment<wmma::accumulator, 16, 16, 8, float> acc[4][2];
#pragma unroll
    for (int i = 0; i < 4; i++)
#pragma unroll
        for (int j = 0; j < 2; j++) wmma::fill_fragment(acc[i][j], 0.0f);

    const bool fullTile = (rowBase + 128 <= nN);

    for (int k0 = 0; k0 < FDIM; k0 += 32) {
        // Load X tile: 128 rows x 32 cols. Thread t: row = t>>1, 16 cols.
        {
            const int m  = tid >> 1;
            const int c0 = (tid & 1) * 16;
            const int gr = rowBase + m;
            float* xrow = &Xs[m * XS_LD + c0];
            if (gr < nN) {
                const float* g = X + (size_t)gr * FDIM + k0 + c0;
#pragma unroll
                for (int j = 0; j < 4; j++)
                    *(float4*)(xrow + j * 4) = *(const float4*)(g + j * 4);
            } else {
#pragma unroll
                for (int j = 0; j < 4; j++)
                    *(float4*)(xrow + j * 4) = make_float4(0.f, 0.f, 0.f, 0.f);
            }
        }
        // Load H tile: 32 rows x 128 cols. Thread t: row = t>>3, 16 cols.
        {
            const int r  = tid >> 3;
            const int c0 = (tid & 7) * 16;
            const float* g = Hk + (size_t)(k0 + r) * FDIM + c0;
            float* hrow = &Hs[r * HS_LD + c0];
#pragma unroll
            for (int j = 0; j < 4; j++)
                *(float4*)(hrow + j * 4) = *(const float4*)(g + j * 4);
        }
        __syncthreads();

#pragma unroll
        for (int kk = 0; kk < 4; kk++) {
            wmma::fragment<wmma::matrix_a, 16, 16, 8, wmma::precision::tf32, wmma::row_major> a[4];
            wmma::fragment<wmma::matrix_b, 16, 16, 8, wmma::precision::tf32, wmma::row_major> b[2];
#pragma unroll
            for (int i = 0; i < 4; i++) {
                wmma::load_matrix_sync(a[i], &Xs[(warpM + i * 16) * XS_LD + kk * 8], XS_LD);
#pragma unroll
                for (int e = 0; e < a[i].num_elements; e++)
                    a[i].x[e] = wmma::__float_to_tf32(a[i].x[e]);
            }
#pragma unroll
            for (int j = 0; j < 2; j++) {
                wmma::load_matrix_sync(b[j], &Hs[(kk * 8) * HS_LD + warpN + j * 16], HS_LD);
#pragma unroll
                for (int e = 0; e < b[j].num_elements; e++)
                    b[j].x[e] = wmma::__float_to_tf32(b[j].x[e]);
            }
#pragma unroll
            for (int i = 0; i < 4; i++)
#pragma unroll
                for (int j = 0; j < 2; j++)
                    wmma::mma_sync(acc[i][j], a[i], b[j], acc[i][j]);
        }
        __syncthreads();
    }

    // Epilogue
    if (fullTile) {
#pragma unroll
        for (int i = 0; i < 4; i++)
#pragma unroll
            for (int j = 0; j < 2; j++) {
                float* d = dst + (size_t)(rowBase + warpM + i * 16) * FDIM + warpN + j * 16;
                wmma::store_matrix_sync(d, acc[i][j], FDIM, wmma::mem_row_major);
            }
    } else {
#pragma unroll
        for (int i = 0; i < 4; i++)
#pragma unroll
            for (int j = 0; j < 2; j++) {
                const int mBase = rowBase + warpM + i * 16;
                if (mBase >= nN) continue;
                if (mBase + 16 <= nN) {
                    float* d = dst + (size_t)mBase * FDIM + warpN + j * 16;
                    wmma::store_matrix_sync(d, acc[i][j], FDIM, wmma::mem_row_major);
                } else {
                    // partial fragment: stage in smem, guarded copy
                    wmma::store_matrix_sync(&Stage[warp][0], acc[i][j], 17, wmma::mem_row_major);
                    __syncwarp();
                    const int r = lane >> 1, c = (lane & 1) * 8;
                    if (mBase + r < nN) {
                        float* d = dst + (size_t)(mBase + r) * FDIM + warpN + j * 16 + c;
#pragma unroll
                        for (int q = 0; q < 8; q++) d[q] = Stage[warp][r * 17 + c + q];
                    }
                    __syncwarp();
                }
            }
    }
}

// ---------------------------------------------------------------------------
// CSR build
// ---------------------------------------------------------------------------
__global__ void hist_kernel(const int* __restrict__ rows, int* __restrict__ cnt, int nE)
{
    int e = blockIdx.x * 256 + threadIdx.x;
    if (e < nE) atomicAdd(&cnt[rows[e]], 1);
}

__global__ __launch_bounds__(256)
void scan1_kernel(const int* __restrict__ cnt, int* __restrict__ pre,
                  int* __restrict__ bsum, int nN)
{
    const int t    = threadIdx.x;
    const int base = blockIdx.x * 1024 + t * 4;
    const int lane = t & 31, warp = t >> 5;

    int v[4];
#pragma unroll
    for (int j = 0; j < 4; j++) v[j] = (base + j < nN) ? cnt[base + j] : 0;
    const int s = v[0] + v[1] + v[2] + v[3];

    int incl = s;
#pragma unroll
    for (int off = 1; off < 32; off <<= 1) {
        int n = __shfl_up_sync(0xFFFFFFFFu, incl, off);
        if (lane >= off) incl += n;
    }

    __shared__ int wsum[8];
    if (lane == 31) wsum[warp] = incl;
    __syncthreads();
    if (t < 8) {
        int w = wsum[t];
        int wincl = w;
#pragma unroll
        for (int off = 1; off < 8; off <<= 1) {
            int n = __shfl_up_sync(0xFFu, wincl, off);
            if (t >= off) wincl += n;
        }
        wsum[t] = wincl - w;
    }
    __syncthreads();

    int run = incl - s + wsum[warp];
#pragma unroll
    for (int j = 0; j < 4; j++) {
        if (base + j < nN) pre[base + j] = run;
        run += v[j];
    }
    if (t == 255) bsum[blockIdx.x] = run;
}

__global__ __launch_bounds__(1024)
void scan2_kernel(int* __restrict__ bsum, int* __restrict__ total_out, int B)
{
    __shared__ int sh[1024];
    const int t = threadIdx.x;
    int v = (t < B) ? bsum[t] : 0;
    sh[t] = v;
    __syncthreads();
    for (int off = 1; off < 1024; off <<= 1) {
        int a = (t >= off) ? sh[t - off] : 0;
        __syncthreads();
        sh[t] += a;
        __syncthreads();
    }
    if (t < B) bsum[t] = sh[t] - v;
    if (t == 1023) *total_out = sh[1023];
}

__global__ void scan3_kernel(int* __restrict__ rowptr, const int* __restrict__ bsum,
                             int* __restrict__ cursor, int nN)
{
    int i = blockIdx.x * 256 + threadIdx.x;
    if (i < nN) {
        int val = rowptr[i] + __ldg(bsum + (i >> 10));
        rowptr[i] = val;
        cursor[i] = val;
    }
}

__global__ void scatter_kernel(const int* __restrict__ rows, const int* __restrict__ cols,
                               const float* __restrict__ vals, int* __restrict__ cursor,
                               int2* __restrict__ ecv, int nE)
{
    int e = blockIdx.x * 256 + threadIdx.x;
    if (e < nE) {
        int r   = rows[e];
        int pos = atomicAdd(&cursor[r], 1);
        ecv[pos] = make_int2(cols[e], __float_as_int(vals[e]));
    }
}

// ---------------------------------------------------------------------------
// SpMM (CSR): warp per dest row, register accumulation, NO atomics.
// ---------------------------------------------------------------------------
__global__ __launch_bounds__(256)
void spmm_csr_kernel(const int* __restrict__ rowptr, const int2* __restrict__ ecv,
                     const float* __restrict__ src, float* __restrict__ dst, int nN)
{
    const int w = (blockIdx.x * 256 + threadIdx.x) >> 5;
    if (w >= nN) return;
    const int lane  = threadIdx.x & 31;
    const int start = __ldg(rowptr + w);
    const int end   = __ldg(rowptr + w + 1);

    float4 acc = make_float4(0.f, 0.f, 0.f, 0.f);

#pragma unroll 4
    for (int i = start; i < end; i++) {
        int2  cv = __ldg(ecv + i);
        float v  = __int_as_float(cv.y);
        float4 s = __ldg((const float4*)(src + (size_t)cv.x * FDIM) + lane);
        acc.x += v * s.x;
        acc.y += v * s.y;
        acc.z += v * s.z;
        acc.w += v * s.w;
    }

    float4* d  = (float4*)(dst + (size_t)w * FDIM) + lane;
    float4 cur = *d;
    cur.x += acc.x; cur.y += acc.y; cur.z += acc.z; cur.w += acc.w;
    *d = cur;
}

// ---------------------------------------------------------------------------
extern "C" void kernel_launch(void* const* d_in, const int* in_sizes, int n_in,
                              void* d_out, int out_size)
{
    const int*   rows = (const int*)d_in[0];
    const int*   cols = (const int*)d_in[1];
    const float* vals = (const float*)d_in[2];
    const float* x    = (const float*)d_in[3];
    const float* H    = (const float*)d_in[4];
    float*       out  = (float*)d_out;

    const int nE = in_sizes[0];
    const int nN = in_sizes[3] / FDIM;

    float *buf1, *buf2;
    int *rowptr, *cursor, *bsum;
    int2 *ecv;
    cudaGetSymbolAddress((void**)&buf1, g_buf1);
    cudaGetSymbolAddress((void**)&buf2, g_buf2);
    cudaGetSymbolAddress((void**)&rowptr, g_rowptr);
    cudaGetSymbolAddress((void**)&cursor, g_cursor);
    cudaGetSymbolAddress((void**)&bsum, g_bsum);
    cudaGetSymbolAddress((void**)&ecv, g_ecv);

    static cudaStream_t sGemm = nullptr;
    static cudaEvent_t  evFork = nullptr, evGemm = nullptr;
    if (sGemm == nullptr) {
        cudaStreamCreateWithFlags(&sGemm, cudaStreamNonBlocking);
        cudaEventCreateWithFlags(&evFork, cudaEventDisableTiming);
        cudaEventCreateWithFlags(&evGemm, cudaEventDisableTiming);
    }

    const int eBlocks = (nE + 255) / 256;
    const int nBlocks = (nN + 255) / 256;
    const int B       = (nN + 1023) / 1024;
    const int mTiles  = (nN + 127) / 128;

    // ---- fork: TF32 GEMM on side stream ----
    cudaEventRecord(evFork, 0);
    cudaStreamWaitEvent(sGemm, evFork, 0);
    gemm3_tf32_kernel<<<dim3(mTiles, 3, 1), 256, 0, sGemm>>>(x, H, out, buf1, buf2, nN);
    cudaEventRecord(evGemm, sGemm);

    // ---- CSR build on main stream (overlaps GEMM) ----
    cudaMemsetAsync(cursor, 0, (size_t)nN * sizeof(int), 0);
    hist_kernel<<<eBlocks, 256>>>(rows, cursor, nE);
    scan1_kernel<<<B, 256>>>(cursor, rowptr, bsum, nN);
    scan2_kernel<<<1, 1024>>>(bsum, rowptr + nN, B);
    scan3_kernel<<<nBlocks, 256>>>(rowptr, bsum, cursor, nN);
    scatter_kernel<<<eBlocks, 256>>>(rows, cols, vals, cursor, ecv, nE);

    // ---- join, then two atomic-free SpMM passes ----
    cudaStreamWaitEvent(0, evGemm, 0);
    const int spmmBlocks = (int)(((long long)nN * 32 + 255) / 256);
    spmm_csr_kernel<<<spmmBlocks, 256>>>(rowptr, ecv, buf2, buf1, nN);  // buf1 = Y1 + A@Y2
    spmm_csr_kernel<<<spmmBlocks, 256>>>(rowptr, ecv, buf1, out, nN);   // out  = Y0 + A@buf1
}

// round 7
// speedup vs baseline: 1.4069x; 1.1327x over previous
#include <cuda_runtime.h>
#include <cuda_fp16.h>
#include <mma.h>
#include <cstdint>

using namespace nvcuda;

// ---------------------------------------------------------------------------
// GCNConv: out = X@H0 + A@(X@H1) + A^2@(X@H2)
//   Restructured:  out = Y0 + A@(Y1 + A@Y2),  [Y0|Y1|Y2] = X @ [H0|H1|H2]
// Round 6: SpMM intermediates (Y2, buf1) stored fp16 -> gather bytes halved.
//   fp32 accumulation everywhere; final out fp32. TF32 tensor-core GEMM.
//   Orchestration: fork CSR build under GEMM, join, SpMM x2 (R3 pattern).
// ---------------------------------------------------------------------------

#define N_NODES_MAX 100000
#define N_EDGES_MAX 3200000
#define FDIM 128

__device__ __align__(16) __half g_buf1[(size_t)N_NODES_MAX * FDIM];  // 25.6 MB
__device__ __align__(16) __half g_buf2[(size_t)N_NODES_MAX * FDIM];  // 25.6 MB
__device__ int   g_rowptr[N_NODES_MAX + 1];
__device__ int   g_cursor[N_NODES_MAX + 1];
__device__ int   g_bsum[1024];
__device__ int2  g_ecv[N_EDGES_MAX];

// ---------------------------------------------------------------------------
// TF32 GEMM: k = blockIdx.y in {0,1,2}. k==0 -> fp32 out; k==1,2 -> fp16 bufs.
// 128x128 tile, BK=32, 8 warps (2x4), warp does 64x32 via 4x2 m16n16k8 frags.
// ---------------------------------------------------------------------------
#define XS_LD 36
#define HS_LD 132
#define ST_LD 20   // staging ldm (multiple of 4 for fp32 wmma store)

__global__ __launch_bounds__(256, 2)
void gemm3_tf32_kernel(const float* __restrict__ X, const float* __restrict__ H,
                       float* __restrict__ out0, __half* __restrict__ out1,
                       __half* __restrict__ out2, int nN)
{
    const int kSel = blockIdx.y;
    const float* Hk = H + (size_t)kSel * FDIM * FDIM;
    const int rowBase = blockIdx.x * 128;

    __shared__ float Xs[128 * XS_LD];
    __shared__ float Hs[32 * HS_LD];
    __shared__ float Stage[8][16 * ST_LD];

    const int tid   = threadIdx.x;
    const int warp  = tid >> 5;
    const int lane  = tid & 31;
    const int warpM = (warp & 1) * 64;
    const int warpN = (warp >> 1) * 32;

    wmma::fragment<wmma::accumulator, 16, 16, 8, float> acc[4][2];
#pragma unroll
    for (int i = 0; i < 4; i++)
#pragma unroll
        for (int j = 0; j < 2; j++) wmma::fill_fragment(acc[i][j], 0.0f);

    for (int k0 = 0; k0 < FDIM; k0 += 32) {
        {
            const int m  = tid >> 1;
            const int c0 = (tid & 1) * 16;
            const int gr = rowBase + m;
            float* xrow = &Xs[m * XS_LD + c0];
            if (gr < nN) {
                const float* g = X + (size_t)gr * FDIM + k0 + c0;
#pragma unroll
                for (int j = 0; j < 4; j++)
                    *(float4*)(xrow + j * 4) = *(const float4*)(g + j * 4);
            } else {
#pragma unroll
                for (int j = 0; j < 4; j++)
                    *(float4*)(xrow + j * 4) = make_float4(0.f, 0.f, 0.f, 0.f);
            }
        }
        {
            const int r  = tid >> 3;
            const int c0 = (tid & 7) * 16;
            const float* g = Hk + (size_t)(k0 + r) * FDIM + c0;
            float* hrow = &Hs[r * HS_LD + c0];
#pragma unroll
            for (int j = 0; j < 4; j++)
                *(float4*)(hrow + j * 4) = *(const float4*)(g + j * 4);
        }
        __syncthreads();

#pragma unroll
        for (int kk = 0; kk < 4; kk++) {
            wmma::fragment<wmma::matrix_a, 16, 16, 8, wmma::precision::tf32, wmma::row_major> a[4];
            wmma::fragment<wmma::matrix_b, 16, 16, 8, wmma::precision::tf32, wmma::row_major> b[2];
#pragma unroll
            for (int i = 0; i < 4; i++) {
                wmma::load_matrix_sync(a[i], &Xs[(warpM + i * 16) * XS_LD + kk * 8], XS_LD);
#pragma unroll
                for (int e = 0; e < a[i].num_elements; e++)
                    a[i].x[e] = wmma::__float_to_tf32(a[i].x[e]);
            }
#pragma unroll
            for (int j = 0; j < 2; j++) {
                wmma::load_matrix_sync(b[j], &Hs[(kk * 8) * HS_LD + warpN + j * 16], HS_LD);
#pragma unroll
                for (int e = 0; e < b[j].num_elements; e++)
                    b[j].x[e] = wmma::__float_to_tf32(b[j].x[e]);
            }
#pragma unroll
            for (int i = 0; i < 4; i++)
#pragma unroll
                for (int j = 0; j < 2; j++)
                    wmma::mma_sync(acc[i][j], a[i], b[j], acc[i][j]);
        }
        __syncthreads();
    }

    // ---- Epilogue ----
    if (kSel == 0) {
        // fp32 -> out
        const bool fullTile = (rowBase + 128 <= nN);
        if (fullTile) {
#pragma unroll
            for (int i = 0; i < 4; i++)
#pragma unroll
                for (int j = 0; j < 2; j++) {
                    float* d = out0 + (size_t)(rowBase + warpM + i * 16) * FDIM + warpN + j * 16;
                    wmma::store_matrix_sync(d, acc[i][j], FDIM, wmma::mem_row_major);
                }
        } else {
#pragma unroll
            for (int i = 0; i < 4; i++)
#pragma unroll
                for (int j = 0; j < 2; j++) {
                    const int mBase = rowBase + warpM + i * 16;
                    if (mBase >= nN) continue;
                    if (mBase + 16 <= nN) {
                        float* d = out0 + (size_t)mBase * FDIM + warpN + j * 16;
                        wmma::store_matrix_sync(d, acc[i][j], FDIM, wmma::mem_row_major);
                    } else {
                        wmma::store_matrix_sync(&Stage[warp][0], acc[i][j], ST_LD, wmma::mem_row_major);
                        __syncwarp();
                        const int r = lane >> 1, c = (lane & 1) * 8;
                        if (mBase + r < nN) {
                            float* d = out0 + (size_t)(mBase + r) * FDIM + warpN + j * 16 + c;
                            const float* s = &Stage[warp][r * ST_LD + c];
#pragma unroll
                            for (int q = 0; q < 8; q++) d[q] = s[q];
                        }
                        __syncwarp();
                    }
                }
        }
    } else {
        // fp16 -> buf1 (k=1) / buf2 (k=2), staged conversion
        __half* dstH = (kSel == 1) ? out1 : out2;
#pragma unroll
        for (int i = 0; i < 4; i++)
#pragma unroll
            for (int j = 0; j < 2; j++) {
                const int mBase = rowBase + warpM + i * 16;
                if (mBase >= nN) continue;
                wmma::store_matrix_sync(&Stage[warp][0], acc[i][j], ST_LD, wmma::mem_row_major);
                __syncwarp();
                const int r = lane >> 1, c = (lane & 1) * 8;
                if (mBase + r < nN) {
                    const float* s = &Stage[warp][r * ST_LD + c];
                    __half2 h0 = __floats2half2_rn(s[0], s[1]);
                    __half2 h1 = __floats2half2_rn(s[2], s[3]);
                    __half2 h2 = __floats2half2_rn(s[4], s[5]);
                    __half2 h3 = __floats2half2_rn(s[6], s[7]);
                    uint4 u;
                    u.x = *(unsigned*)&h0; u.y = *(unsigned*)&h1;
                    u.z = *(unsigned*)&h2; u.w = *(unsigned*)&h3;
                    *(uint4*)(dstH + (size_t)(mBase + r) * FDIM + warpN + j * 16 + c) = u;
                }
                __syncwarp();
            }
    }
}

// ---------------------------------------------------------------------------
// CSR build
// ---------------------------------------------------------------------------
__global__ void hist_kernel(const int* __restrict__ rows, int* __restrict__ cnt, int nE)
{
    int e = blockIdx.x * 256 + threadIdx.x;
    if (e < nE) atomicAdd(&cnt[rows[e]], 1);
}

__global__ __launch_bounds__(256)
void scan1_kernel(const int* __restrict__ cnt, int* __restrict__ pre,
                  int* __restrict__ bsum, int nN)
{
    const int t    = threadIdx.x;
    const int base = blockIdx.x * 1024 + t * 4;
    const int lane = t & 31, warp = t >> 5;

    int v[4];
#pragma unroll
    for (int j = 0; j < 4; j++) v[j] = (base + j < nN) ? cnt[base + j] : 0;
    const int s = v[0] + v[1] + v[2] + v[3];

    int incl = s;
#pragma unroll
    for (int off = 1; off < 32; off <<= 1) {
        int n = __shfl_up_sync(0xFFFFFFFFu, incl, off);
        if (lane >= off) incl += n;
    }

    __shared__ int wsum[8];
    if (lane == 31) wsum[warp] = incl;
    __syncthreads();
    if (t < 8) {
        int w = wsum[t];
        int wincl = w;
#pragma unroll
        for (int off = 1; off < 8; off <<= 1) {
            int n = __shfl_up_sync(0xFFu, wincl, off);
            if (t >= off) wincl += n;
        }
        wsum[t] = wincl - w;
    }
    __syncthreads();

    int run = incl - s + wsum[warp];
#pragma unroll
    for (int j = 0; j < 4; j++) {
        if (base + j < nN) pre[base + j] = run;
        run += v[j];
    }
    if (t == 255) bsum[blockIdx.x] = run;
}

__global__ __launch_bounds__(1024)
void scan2_kernel(int* __restrict__ bsum, int* __restrict__ total_out, int B)
{
    __shared__ int sh[1024];
    const int t = threadIdx.x;
    int v = (t < B) ? bsum[t] : 0;
    sh[t] = v;
    __syncthreads();
    for (int off = 1; off < 1024; off <<= 1) {
        int a = (t >= off) ? sh[t - off] : 0;
        __syncthreads();
        sh[t] += a;
        __syncthreads();
    }
    if (t < B) bsum[t] = sh[t] - v;
    if (t == 1023) *total_out = sh[1023];
}

__global__ void scan3_kernel(int* __restrict__ rowptr, const int* __restrict__ bsum,
                             int* __restrict__ cursor, int nN)
{
    int i = blockIdx.x * 256 + threadIdx.x;
    if (i < nN) {
        int val = rowptr[i] + __ldg(bsum + (i >> 10));
        rowptr[i] = val;
        cursor[i] = val;
    }
}

__global__ void scatter_kernel(const int* __restrict__ rows, const int* __restrict__ cols,
                               const float* __restrict__ vals, int* __restrict__ cursor,
                               int2* __restrict__ ecv, int nE)
{
    int e = blockIdx.x * 256 + threadIdx.x;
    if (e < nE) {
        int r   = rows[e];
        int pos = atomicAdd(&cursor[r], 1);
        ecv[pos] = make_int2(cols[e], __float_as_int(vals[e]));
    }
}

// ---------------------------------------------------------------------------
// SpMM (CSR), warp per row, fp16 gather / fp32 accumulate.
// h2h: dst fp16 (pass 1), h2f: dst fp32 (pass 2).
// ---------------------------------------------------------------------------
__global__ __launch_bounds__(256)
void spmm_h2h_kernel(const int* __restrict__ rowptr, const int2* __restrict__ ecv,
                     const __half* __restrict__ src, __half* __restrict__ dst, int nN)
{
    const int w = (blockIdx.x * 256 + threadIdx.x) >> 5;
    if (w >= nN) return;
    const int lane  = threadIdx.x & 31;
    const int start = __ldg(rowptr + w);
    const int end   = __ldg(rowptr + w + 1);

    float4 acc = make_float4(0.f, 0.f, 0.f, 0.f);

#pragma unroll 4
    for (int i = start; i < end; i++) {
        int2  cv = __ldg(ecv + i);
        float v  = __int_as_float(cv.y);
        uint2 p  = __ldg((const uint2*)(src + (size_t)cv.x * FDIM) + lane);
        float2 f0 = __half22float2(*(__half2*)&p.x);
        float2 f1 = __half22float2(*(__half2*)&p.y);
        acc.x += v * f0.x;
        acc.y += v * f0.y;
        acc.z += v * f1.x;
        acc.w += v * f1.y;
    }

    uint2* d  = (uint2*)(dst + (size_t)w * FDIM) + lane;
    uint2 cur = *d;
    float2 g0 = __half22float2(*(__half2*)&cur.x);
    float2 g1 = __half22float2(*(__half2*)&cur.y);
    g0.x += acc.x; g0.y += acc.y; g1.x += acc.z; g1.y += acc.w;
    __half2 o0 = __floats2half2_rn(g0.x, g0.y);
    __half2 o1 = __floats2half2_rn(g1.x, g1.y);
    uint2 o;
    o.x = *(unsigned*)&o0;
    o.y = *(unsigned*)&o1;
    *d = o;
}

__global__ __launch_bounds__(256)
void spmm_h2f_kernel(const int* __restrict__ rowptr, const int2* __restrict__ ecv,
                     const __half* __restrict__ src, float* __restrict__ dst, int nN)
{
    const int w = (blockIdx.x * 256 + threadIdx.x) >> 5;
    if (w >= nN) return;
    const int lane  = threadIdx.x & 31;
    const int start = __ldg(rowptr + w);
    const int end   = __ldg(rowptr + w + 1);

    float4 acc = make_float4(0.f, 0.f, 0.f, 0.f);

#pragma unroll 4
    for (int i = start; i < end; i++) {
        int2  cv = __ldg(ecv + i);
        float v  = __int_as_float(cv.y);
        uint2 p  = __ldg((const uint2*)(src + (size_t)cv.x * FDIM) + lane);
        float2 f0 = __half22float2(*(__half2*)&p.x);
        float2 f1 = __half22float2(*(__half2*)&p.y);
        acc.x += v * f0.x;
        acc.y += v * f0.y;
        acc.z += v * f1.x;
        acc.w += v * f1.y;
    }

    float4* d  = (float4*)(dst + (size_t)w * FDIM) + lane;
    float4 cur = *d;
    cur.x += acc.x; cur.y += acc.y; cur.z += acc.z; cur.w += acc.w;
    *d = cur;
}

// ---------------------------------------------------------------------------
extern "C" void kernel_launch(void* const* d_in, const int* in_sizes, int n_in,
                              void* d_out, int out_size)
{
    const int*   rows = (const int*)d_in[0];
    const int*   cols = (const int*)d_in[1];
    const float* vals = (const float*)d_in[2];
    const float* x    = (const float*)d_in[3];
    const float* H    = (const float*)d_in[4];
    float*       out  = (float*)d_out;

    const int nE = in_sizes[0];
    const int nN = in_sizes[3] / FDIM;

    __half *buf1, *buf2;
    int *rowptr, *cursor, *bsum;
    int2 *ecv;
    cudaGetSymbolAddress((void**)&buf1, g_buf1);
    cudaGetSymbolAddress((void**)&buf2, g_buf2);
    cudaGetSymbolAddress((void**)&rowptr, g_rowptr);
    cudaGetSymbolAddress((void**)&cursor, g_cursor);
    cudaGetSymbolAddress((void**)&bsum, g_bsum);
    cudaGetSymbolAddress((void**)&ecv, g_ecv);

    static cudaStream_t sGemm = nullptr;
    static cudaEvent_t  evFork = nullptr, evGemm = nullptr;
    if (sGemm == nullptr) {
        cudaStreamCreateWithFlags(&sGemm, cudaStreamNonBlocking);
        cudaEventCreateWithFlags(&evFork, cudaEventDisableTiming);
        cudaEventCreateWithFlags(&evGemm, cudaEventDisableTiming);
    }

    const int eBlocks = (nE + 255) / 256;
    const int nBlocks = (nN + 255) / 256;
    const int B       = (nN + 1023) / 1024;
    const int mTiles  = (nN + 127) / 128;

    // ---- fork: TF32 GEMM on side stream ----
    cudaEventRecord(evFork, 0);
    cudaStreamWaitEvent(sGemm, evFork, 0);
    gemm3_tf32_kernel<<<dim3(mTiles, 3, 1), 256, 0, sGemm>>>(x, H, out, buf1, buf2, nN);
    cudaEventRecord(evGemm, sGemm);

    // ---- CSR build on main stream (overlaps GEMM) ----
    cudaMemsetAsync(cursor, 0, (size_t)nN * sizeof(int), 0);
    hist_kernel<<<eBlocks, 256>>>(rows, cursor, nE);
    scan1_kernel<<<B, 256>>>(cursor, rowptr, bsum, nN);
    scan2_kernel<<<1, 1024>>>(bsum, rowptr + nN, B);
    scan3_kernel<<<nBlocks, 256>>>(rowptr, bsum, cursor, nN);
    scatter_kernel<<<eBlocks, 256>>>(rows, cols, vals, cursor, ecv, nE);

    // ---- join, then two SpMM passes (fp16 gather, fp32 accumulate) ----
    cudaStreamWaitEvent(0, evGemm, 0);
    const int spmmBlocks = (int)(((long long)nN * 32 + 255) / 256);
    spmm_h2h_kernel<<<spmmBlocks, 256>>>(rowptr, ecv, buf2, buf1, nN);  // buf1 = Y1 + A@Y2
    spmm_h2f_kernel<<<spmmBlocks, 256>>>(rowptr, ecv, buf1, out, nN);   // out  = Y0 + A@buf1
}

// round 8
// speedup vs baseline: 1.7762x; 1.2625x over previous
#include <cuda_runtime.h>
#include <cuda_fp16.h>
#include <mma.h>
#include <cstdint>

using namespace nvcuda;

// ---------------------------------------------------------------------------
// GCNConv: out = X@H0 + A@(X@H1) + A^2@(X@H2)
//   Restructured:  out = Y0 + A@(Y1 + A@Y2),  [Y0|Y1|Y2] = X @ [H0|H1|H2]
// Round 8: GEMM moves to fp16 wmma m16n16k16 (same 10-bit mantissa as TF32,
//   ~2x rate, half the fragments; convert at smem fill, not in mainloop).
//   SpMM intermediates fp16, fp32 accumulate. Fork CSR build under GEMM.
// ---------------------------------------------------------------------------

#define N_NODES_MAX 100000
#define N_EDGES_MAX 3200000
#define FDIM 128

__device__ __align__(16) __half g_buf1[(size_t)N_NODES_MAX * FDIM];  // 25.6 MB
__device__ __align__(16) __half g_buf2[(size_t)N_NODES_MAX * FDIM];  // 25.6 MB
__device__ int   g_rowptr[N_NODES_MAX + 1];
__device__ int   g_cursor[N_NODES_MAX + 1];
__device__ int   g_bsum[1024];
__device__ int2  g_ecv[N_EDGES_MAX];

// ---------------------------------------------------------------------------
// fp16 GEMM: k = blockIdx.y in {0,1,2}. k==0 -> fp32 out; k==1,2 -> fp16 bufs.
// 128x128 tile, BK=32, 8 warps (2x4), warp does 64x32 via 4x2 m16n16k16.
// ---------------------------------------------------------------------------
#define XS_LD 40    // halves; 80B row stride (multiple of 16B)
#define HS_LD 136   // halves; 272B row stride (multiple of 16B)
#define ST_LD 20    // float staging ldm

__global__ __launch_bounds__(256, 2)
void gemm3_h_kernel(const float* __restrict__ X, const float* __restrict__ H,
                    float* __restrict__ out0, __half* __restrict__ out1,
                    __half* __restrict__ out2, int nN)
{
    const int kSel = blockIdx.y;
    const float* Hk = H + (size_t)kSel * FDIM * FDIM;
    const int rowBase = blockIdx.x * 128;

    __shared__ __half Xs[128 * XS_LD];
    __shared__ __half Hs[32 * HS_LD];
    __shared__ float  Stage[8][16 * ST_LD];

    const int tid   = threadIdx.x;
    const int warp  = tid >> 5;
    const int lane  = tid & 31;
    const int warpM = (warp & 1) * 64;
    const int warpN = (warp >> 1) * 32;

    wmma::fragment<wmma::accumulator, 16, 16, 16, float> acc[4][2];
#pragma unroll
    for (int i = 0; i < 4; i++)
#pragma unroll
        for (int j = 0; j < 2; j++) wmma::fill_fragment(acc[i][j], 0.0f);

    for (int k0 = 0; k0 < FDIM; k0 += 32) {
        // X tile: 128 rows x 32 cols fp32 -> fp16 smem. Thread: row=tid>>1, 16 cols.
        {
            const int m  = tid >> 1;
            const int c0 = (tid & 1) * 16;
            const int gr = rowBase + m;
            __half2 h[8];
            if (gr < nN) {
                const float* g = X + (size_t)gr * FDIM + k0 + c0;
#pragma unroll
                for (int j = 0; j < 4; j++) {
                    float4 v = *(const float4*)(g + j * 4);
                    h[j * 2 + 0] = __floats2half2_rn(v.x, v.y);
                    h[j * 2 + 1] = __floats2half2_rn(v.z, v.w);
                }
            } else {
#pragma unroll
                for (int j = 0; j < 8; j++) h[j] = __floats2half2_rn(0.f, 0.f);
            }
            uint4* dst = (uint4*)&Xs[m * XS_LD + c0];
            uint4 u0, u1;
            u0.x = *(unsigned*)&h[0]; u0.y = *(unsigned*)&h[1];
            u0.z = *(unsigned*)&h[2]; u0.w = *(unsigned*)&h[3];
            u1.x = *(unsigned*)&h[4]; u1.y = *(unsigned*)&h[5];
            u1.z = *(unsigned*)&h[6]; u1.w = *(unsigned*)&h[7];
            dst[0] = u0; dst[1] = u1;
        }
        // H tile: 32 rows x 128 cols fp32 -> fp16 smem. Thread: row=tid>>3, 16 cols.
        {
            const int r  = tid >> 3;
            const int c0 = (tid & 7) * 16;
            const float* g = Hk + (size_t)(k0 + r) * FDIM + c0;
            __half2 h[8];
#pragma unroll
            for (int j = 0; j < 4; j++) {
                float4 v = *(const float4*)(g + j * 4);
                h[j * 2 + 0] = __floats2half2_rn(v.x, v.y);
                h[j * 2 + 1] = __floats2half2_rn(v.z, v.w);
            }
            uint4* dst = (uint4*)&Hs[r * HS_LD + c0];
            uint4 u0, u1;
            u0.x = *(unsigned*)&h[0]; u0.y = *(unsigned*)&h[1];
            u0.z = *(unsigned*)&h[2]; u0.w = *(unsigned*)&h[3];
            u1.x = *(unsigned*)&h[4]; u1.y = *(unsigned*)&h[5];
            u1.z = *(unsigned*)&h[6]; u1.w = *(unsigned*)&h[7];
            dst[0] = u0; dst[1] = u1;
        }
        __syncthreads();

#pragma unroll
        for (int kk = 0; kk < 2; kk++) {
            wmma::fragment<wmma::matrix_a, 16, 16, 16, __half, wmma::row_major> a[4];
            wmma::fragment<wmma::matrix_b, 16, 16, 16, __half, wmma::row_major> b[2];
#pragma unroll
            for (int i = 0; i < 4; i++)
                wmma::load_matrix_sync(a[i], &Xs[(warpM + i * 16) * XS_LD + kk * 16], XS_LD);
#pragma unroll
            for (int j = 0; j < 2; j++)
                wmma::load_matrix_sync(b[j], &Hs[(kk * 16) * HS_LD + warpN + j * 16], HS_LD);
#pragma unroll
            for (int i = 0; i < 4; i++)
#pragma unroll
                for (int j = 0; j < 2; j++)
                    wmma::mma_sync(acc[i][j], a[i], b[j], acc[i][j]);
        }
        __syncthreads();
    }

    // ---- Epilogue ----
    if (kSel == 0) {
        const bool fullTile = (rowBase + 128 <= nN);
        if (fullTile) {
#pragma unroll
            for (int i = 0; i < 4; i++)
#pragma unroll
                for (int j = 0; j < 2; j++) {
                    float* d = out0 + (size_t)(rowBase + warpM + i * 16) * FDIM + warpN + j * 16;
                    wmma::store_matrix_sync(d, acc[i][j], FDIM, wmma::mem_row_major);
                }
        } else {
#pragma unroll
            for (int i = 0; i < 4; i++)
#pragma unroll
                for (int j = 0; j < 2; j++) {
                    const int mBase = rowBase + warpM + i * 16;
                    if (mBase >= nN) continue;
                    if (mBase + 16 <= nN) {
                        float* d = out0 + (size_t)mBase * FDIM + warpN + j * 16;
                        wmma::store_matrix_sync(d, acc[i][j], FDIM, wmma::mem_row_major);
                    } else {
                        wmma::store_matrix_sync(&Stage[warp][0], acc[i][j], ST_LD, wmma::mem_row_major);
                        __syncwarp();
                        const int r = lane >> 1, c = (lane & 1) * 8;
                        if (mBase + r < nN) {
                            float* d = out0 + (size_t)(mBase + r) * FDIM + warpN + j * 16 + c;
                            const float* s = &Stage[warp][r * ST_LD + c];
#pragma unroll
                            for (int q = 0; q < 8; q++) d[q] = s[q];
                        }
                        __syncwarp();
                    }
                }
        }
    } else {
        __half* dstH = (kSel == 1) ? out1 : out2;
#pragma unroll
        for (int i = 0; i < 4; i++)
#pragma unroll
            for (int j = 0; j < 2; j++) {
                const int mBase = rowBase + warpM + i * 16;
                if (mBase >= nN) continue;
                wmma::store_matrix_sync(&Stage[warp][0], acc[i][j], ST_LD, wmma::mem_row_major);
                __syncwarp();
                const int r = lane >> 1, c = (lane & 1) * 8;
                if (mBase + r < nN) {
                    const float* s = &Stage[warp][r * ST_LD + c];
                    __half2 h0 = __floats2half2_rn(s[0], s[1]);
                    __half2 h1 = __floats2half2_rn(s[2], s[3]);
                    __half2 h2 = __floats2half2_rn(s[4], s[5]);
                    __half2 h3 = __floats2half2_rn(s[6], s[7]);
                    uint4 u;
                    u.x = *(unsigned*)&h0; u.y = *(unsigned*)&h1;
                    u.z = *(unsigned*)&h2; u.w = *(unsigned*)&h3;
                    *(uint4*)(dstH + (size_t)(mBase + r) * FDIM + warpN + j * 16 + c) = u;
                }
                __syncwarp();
            }
    }
}

// ---------------------------------------------------------------------------
// CSR build
// ---------------------------------------------------------------------------
__global__ void hist_kernel(const int* __restrict__ rows, int* __restrict__ cnt, int nE)
{
    int e = blockIdx.x * 256 + threadIdx.x;
    if (e < nE) atomicAdd(&cnt[rows[e]], 1);
}

__global__ __launch_bounds__(256)
void scan1_kernel(const int* __restrict__ cnt, int* __restrict__ pre,
                  int* __restrict__ bsum, int nN)
{
    const int t    = threadIdx.x;
    const int base = blockIdx.x * 1024 + t * 4;
    const int lane = t & 31, warp = t >> 5;

    int v[4];
#pragma unroll
    for (int j = 0; j < 4; j++) v[j] = (base + j < nN) ? cnt[base + j] : 0;
    const int s = v[0] + v[1] + v[2] + v[3];

    int incl = s;
#pragma unroll
    for (int off = 1; off < 32; off <<= 1) {
        int n = __shfl_up_sync(0xFFFFFFFFu, incl, off);
        if (lane >= off) incl += n;
    }

    __shared__ int wsum[8];
    if (lane == 31) wsum[warp] = incl;
    __syncthreads();
    if (t < 8) {
        int w = wsum[t];
        int wincl = w;
#pragma unroll
        for (int off = 1; off < 8; off <<= 1) {
            int n = __shfl_up_sync(0xFFu, wincl, off);
            if (t >= off) wincl += n;
        }
        wsum[t] = wincl - w;
    }
    __syncthreads();

    int run = incl - s + wsum[warp];
#pragma unroll
    for (int j = 0; j < 4; j++) {
        if (base + j < nN) pre[base + j] = run;
        run += v[j];
    }
    if (t == 255) bsum[blockIdx.x] = run;
}

__global__ __launch_bounds__(1024)
void scan2_kernel(int* __restrict__ bsum, int* __restrict__ total_out, int B)
{
    __shared__ int sh[1024];
    const int t = threadIdx.x;
    int v = (t < B) ? bsum[t] : 0;
    sh[t] = v;
    __syncthreads();
    for (int off = 1; off < 1024; off <<= 1) {
        int a = (t >= off) ? sh[t - off] : 0;
        __syncthreads();
        sh[t] += a;
        __syncthreads();
    }
    if (t < B) bsum[t] = sh[t] - v;
    if (t == 1023) *total_out = sh[1023];
}

__global__ void scan3_kernel(int* __restrict__ rowptr, const int* __restrict__ bsum,
                             int* __restrict__ cursor, int nN)
{
    int i = blockIdx.x * 256 + threadIdx.x;
    if (i < nN) {
        int val = rowptr[i] + __ldg(bsum + (i >> 10));
        rowptr[i] = val;
        cursor[i] = val;
    }
}

__global__ void scatter_kernel(const int* __restrict__ rows, const int* __restrict__ cols,
                               const float* __restrict__ vals, int* __restrict__ cursor,
                               int2* __restrict__ ecv, int nE)
{
    int e = blockIdx.x * 256 + threadIdx.x;
    if (e < nE) {
        int r   = rows[e];
        int pos = atomicAdd(&cursor[r], 1);
        ecv[pos] = make_int2(cols[e], __float_as_int(vals[e]));
    }
}

// ---------------------------------------------------------------------------
// SpMM (CSR), warp per row, fp16 gather / fp32 accumulate.
// ---------------------------------------------------------------------------
__global__ __launch_bounds__(256)
void spmm_h2h_kernel(const int* __restrict__ rowptr, const int2* __restrict__ ecv,
                     const __half* __restrict__ src, __half* __restrict__ dst, int nN)
{
    const int w = (blockIdx.x * 256 + threadIdx.x) >> 5;
    if (w >= nN) return;
    const int lane  = threadIdx.x & 31;
    const int start = __ldg(rowptr + w);
    const int end   = __ldg(rowptr + w + 1);

    float4 acc = make_float4(0.f, 0.f, 0.f, 0.f);

#pragma unroll 4
    for (int i = start; i < end; i++) {
        int2  cv = __ldg(ecv + i);
        float v  = __int_as_float(cv.y);
        uint2 p  = __ldg((const uint2*)(src + (size_t)cv.x * FDIM) + lane);
        float2 f0 = __half22float2(*(__half2*)&p.x);
        float2 f1 = __half22float2(*(__half2*)&p.y);
        acc.x += v * f0.x;
        acc.y += v * f0.y;
        acc.z += v * f1.x;
        acc.w += v * f1.y;
    }

    uint2* d  = (uint2*)(dst + (size_t)w * FDIM) + lane;
    uint2 cur = *d;
    float2 g0 = __half22float2(*(__half2*)&cur.x);
    float2 g1 = __half22float2(*(__half2*)&cur.y);
    g0.x += acc.x; g0.y += acc.y; g1.x += acc.z; g1.y += acc.w;
    __half2 o0 = __floats2half2_rn(g0.x, g0.y);
    __half2 o1 = __floats2half2_rn(g1.x, g1.y);
    uint2 o;
    o.x = *(unsigned*)&o0;
    o.y = *(unsigned*)&o1;
    *d = o;
}

__global__ __launch_bounds__(256)
void spmm_h2f_kernel(const int* __restrict__ rowptr, const int2* __restrict__ ecv,
                     const __half* __restrict__ src, float* __restrict__ dst, int nN)
{
    const int w = (blockIdx.x * 256 + threadIdx.x) >> 5;
    if (w >= nN) return;
    const int lane  = threadIdx.x & 31;
    const int start = __ldg(rowptr + w);
    const int end   = __ldg(rowptr + w + 1);

    float4 acc = make_float4(0.f, 0.f, 0.f, 0.f);

#pragma unroll 4
    for (int i = start; i < end; i++) {
        int2  cv = __ldg(ecv + i);
        float v  = __int_as_float(cv.y);
        uint2 p  = __ldg((const uint2*)(src + (size_t)cv.x * FDIM) + lane);
        float2 f0 = __half22float2(*(__half2*)&p.x);
        float2 f1 = __half22float2(*(__half2*)&p.y);
        acc.x += v * f0.x;
        acc.y += v * f0.y;
        acc.z += v * f1.x;
        acc.w += v * f1.y;
    }

    float4* d  = (float4*)(dst + (size_t)w * FDIM) + lane;
    float4 cur = *d;
    cur.x += acc.x; cur.y += acc.y; cur.z += acc.z; cur.w += acc.w;
    *d = cur;
}

// ---------------------------------------------------------------------------
extern "C" void kernel_launch(void* const* d_in, const int* in_sizes, int n_in,
                              void* d_out, int out_size)
{
    const int*   rows = (const int*)d_in[0];
    const int*   cols = (const int*)d_in[1];
    const float* vals = (const float*)d_in[2];
    const float* x    = (const float*)d_in[3];
    const float* H    = (const float*)d_in[4];
    float*       out  = (float*)d_out;

    const int nE = in_sizes[0];
    const int nN = in_sizes[3] / FDIM;

    __half *buf1, *buf2;
    int *rowptr, *cursor, *bsum;
    int2 *ecv;
    cudaGetSymbolAddress((void**)&buf1, g_buf1);
    cudaGetSymbolAddress((void**)&buf2, g_buf2);
    cudaGetSymbolAddress((void**)&rowptr, g_rowptr);
    cudaGetSymbolAddress((void**)&cursor, g_cursor);
    cudaGetSymbolAddress((void**)&bsum, g_bsum);
    cudaGetSymbolAddress((void**)&ecv, g_ecv);

    static cudaStream_t sGemm = nullptr;
    static cudaEvent_t  evFork = nullptr, evGemm = nullptr;
    if (sGemm == nullptr) {
        cudaStreamCreateWithFlags(&sGemm, cudaStreamNonBlocking);
        cudaEventCreateWithFlags(&evFork, cudaEventDisableTiming);
        cudaEventCreateWithFlags(&evGemm, cudaEventDisableTiming);
    }

    const int eBlocks = (nE + 255) / 256;
    const int nBlocks = (nN + 255) / 256;
    const int B       = (nN + 1023) / 1024;
    const int mTiles  = (nN + 127) / 128;

    // ---- fork: fp16 GEMM on side stream ----
    cudaEventRecord(evFork, 0);
    cudaStreamWaitEvent(sGemm, evFork, 0);
    gemm3_h_kernel<<<dim3(mTiles, 3, 1), 256, 0, sGemm>>>(x, H, out, buf1, buf2, nN);
    cudaEventRecord(evGemm, sGemm);

    // ---- CSR build on main stream (overlaps GEMM) ----
    cudaMemsetAsync(cursor, 0, (size_t)nN * sizeof(int), 0);
    hist_kernel<<<eBlocks, 256>>>(rows, cursor, nE);
    scan1_kernel<<<B, 256>>>(cursor, rowptr, bsum, nN);
    scan2_kernel<<<1, 1024>>>(bsum, rowptr + nN, B);
    scan3_kernel<<<nBlocks, 256>>>(rowptr, bsum, cursor, nN);
    scatter_kernel<<<eBlocks, 256>>>(rows, cols, vals, cursor, ecv, nE);

    // ---- join, then two SpMM passes ----
    cudaStreamWaitEvent(0, evGemm, 0);
    const int spmmBlocks = (int)(((long long)nN * 32 + 255) / 256);
    spmm_h2h_kernel<<<spmmBlocks, 256>>>(rowptr, ecv, buf2, buf1, nN);  // buf1 = Y1 + A@Y2
    spmm_h2f_kernel<<<spmmBlocks, 256>>>(rowptr, ecv, buf1, out, nN);   // out  = Y0 + A@buf1
}